// round 8
// baseline (speedup 1.0000x reference)
#include <cuda_runtime.h>
#include <math.h>
#include <stdint.h>

// ---------------- problem constants ----------------
#define NB      32
#define FH      11
#define FW      20
#define NEDGE   42
#define NANG    17
#define NPRED   77
#define NPROP   714
#define NOFF    72
#define KBACK   512
#define KCONV   1024
#define NREG    1241
#define NCLS    34
#define NPAD    1280        // NREG + NCLS padded to 128
#define MROWS   1344        // NB * NEDGE
#define MPAD    1408        // 11 * 128
#define NWORDS  23
#define NSTRIPSF 71.0f
#define NMS_T   15.0f
#define NCHUNK  128
#define NCHUNKS 6
#define KC      16          // K per pipeline chunk (2 k8 mma steps)
#define SROW    24          // smem row stride in floats (bank-conflict-free LDS.64)
#define MATOFF  3072        // 128 * SROW
#define STAGEF  12288       // 4 * MATOFF floats per stage

// ---------------- scratch ----------------
__device__ float    g_featH [MPAD * KBACK];     // tf32-hi edge features, k-interleaved
__device__ float    g_featL [MPAD * KBACK];
__device__ float    g_WconvH[KCONV * KBACK];
__device__ float    g_WconvL[KCONV * KBACK];
__device__ float    g_convH [MPAD * KCONV];     // gemm1 output, split + interleaved
__device__ float    g_convL [MPAD * KCONV];
__device__ float    g_WcH   [NPAD * KCONV];     // packed W_reg|W_cls, split + interleaved
__device__ float    g_WcL   [NPAD * KCONV];
__device__ float    g_bc    [NPAD];
__device__ float    g_rc    [MPAD * NPAD];      // fused reg|cls output (plain layout)
__device__ int      g_order [NB * NPROP];
__device__ float    g_sstart[NB * NPROP];
__device__ float    g_send  [NB * NPROP];
__device__ float    g_sxs   [NB * NPROP * NOFF];
__device__ unsigned g_sup   [NB * NPROP * NWORDS];

// ---------------- helpers ----------------
__device__ __forceinline__ void split2(float x, uint32_t& h, uint32_t& l) {
    asm("cvt.rna.tf32.f32 %0, %1;" : "=r"(h) : "f"(x));
    float r = x - __uint_as_float(h);
    asm("cvt.rna.tf32.f32 %0, %1;" : "=r"(l) : "f"(r));
}
// interleave within 8-group: j -> (j<4) ? 2j : 2j-7   (0,4,1,5,2,6,3,7 order)
__device__ __forceinline__ int perm8(int j) { return (j < 4) ? 2 * j : 2 * j - 7; }
__device__ __forceinline__ uint32_t smem_u32(const void* p) {
    uint32_t a;
    asm("{ .reg .u64 tmp; cvta.to.shared.u64 tmp, %1; cvt.u32.u64 %0, tmp; }"
        : "=r"(a) : "l"(p));
    return a;
}
#define MMA_TF32(d, a, b)                                                        \
    asm volatile("mma.sync.aligned.m16n8k8.row.col.f32.tf32.tf32.f32 "           \
        "{%0,%1,%2,%3}, {%4,%5,%6,%7}, {%8,%9}, {%0,%1,%2,%3};"                  \
        : "+f"((d)[0]), "+f"((d)[1]), "+f"((d)[2]), "+f"((d)[3])                 \
        : "r"((a)[0]), "r"((a)[1]), "r"((a)[2]), "r"((a)[3]),                    \
          "r"((b)[0]), "r"((b)[1]))
#define CPA_COMMIT() asm volatile("cp.async.commit_group;" ::: "memory")
#define CPA_WAIT1()  asm volatile("cp.async.wait_group 1;" ::: "memory")

// ---------------- pack combined weights (reg | cls | pad), split + interleave ----------------
__global__ void k_packW(const float* __restrict__ Wr, const float* __restrict__ br,
                        const float* __restrict__ Wc, const float* __restrict__ bc) {
    int i = blockIdx.x * blockDim.x + threadIdx.x;
    if (i < NPAD * KCONV) {
        int row = i >> 10, k = i & 1023;
        float v = 0.f;
        if (row < NREG)             v = Wr[(size_t)row * KCONV + k];
        else if (row < NREG + NCLS) v = Wc[(size_t)(row - NREG) * KCONV + k];
        uint32_t h, l;
        split2(v, h, l);
        int dst = (i & ~7) | perm8(i & 7);
        g_WcH[dst] = __uint_as_float(h);
        g_WcL[dst] = __uint_as_float(l);
    }
    if (i < NPAD) {
        float v = 0.f;
        if (i < NREG)             v = br[i];
        else if (i < NREG + NCLS) v = bc[i - NREG];
        g_bc[i] = v;
    }
}

// ---------------- split + interleave W_conv ----------------
__global__ void k_splitW(const float* __restrict__ W) {
    int i = blockIdx.x * blockDim.x + threadIdx.x;
    if (i >= KCONV * KBACK) return;
    uint32_t h, l;
    split2(W[i], h, l);
    int dst = (i & ~7) | perm8(i & 7);
    g_WconvH[dst] = __uint_as_float(h);
    g_WconvL[dst] = __uint_as_float(l);
}

// ---------------- gather edge features, split + interleave ----------------
__global__ void k_gather(const float* __restrict__ feat) {
    int x = blockIdx.x * blockDim.x + threadIdx.x;
    if (x >= KBACK * MROWS) return;
    int c = x & (KBACK - 1);
    int m = x >> 9;
    int b = m / NEDGE, e = m % NEDGE;
    int h, w;
    if (e < FH)        { h = e;      w = 0;        }
    else if (e < 2*FH) { h = e - FH; w = FW - 1;   }
    else               { h = FH - 1; w = e - 2*FH; }
    float v = feat[((size_t)(b * KBACK + c) * FH + h) * FW + w];
    uint32_t hi, lo;
    split2(v, hi, lo);
    int dst = (x & ~7) | perm8(x & 7);
    g_featH[dst] = __uint_as_float(hi);
    g_featL[dst] = __uint_as_float(lo);
}

// ---------------- tf32 mma.sync GEMM, 3xTF32, cp.async 3-stage, LDS.64 frags ----------------
// C[m][n] = sum_k A[m][k] * W[n][k] + bias[n]; operands pre-split + k-interleaved.
// CTA tile 128x128, 8 warps (warp tile 32x64). SPLIT=1: emit split+interleaved hi/lo.
template<int SPLIT>
__global__ __launch_bounds__(256, 1) void k_gemm_mma(
    const float* __restrict__ Ah, const float* __restrict__ Al,
    const float* __restrict__ Bh, const float* __restrict__ Bl,
    const float* __restrict__ bias,
    float* __restrict__ C, float* __restrict__ Ch, float* __restrict__ Cl,
    int K, int N)
{
    extern __shared__ float smf[];
    const uint32_t sbase = smem_u32(smf);
    const int m0 = blockIdx.y * 128, n0 = blockIdx.x * 128;
    const int t = threadIdx.x, w = t >> 5, lane = t & 31;
    const int g = lane >> 2, c = lane & 3;
    const int wm = w & 3, wn = w >> 2;          // warp tile: rows wm*32, cols wn*64

    const float* srcs[4] = {
        Ah + (size_t)m0 * K, Al + (size_t)m0 * K,
        Bh + (size_t)n0 * K, Bl + (size_t)n0 * K };

    auto issue = [&](int ch, int st) {
        int kb = ch * KC;
#pragma unroll
        for (int i = 0; i < 8; i++) {
            int mat = i >> 1;
            int idx = t + (i & 1) * 256;
            int row = idx >> 2, j4 = idx & 3;
            const float* src = srcs[mat] + (size_t)row * K + kb + j4 * 4;
            uint32_t dst = sbase + (uint32_t)((st * STAGEF + mat * MATOFF + row * SROW + j4 * 4) << 2);
            asm volatile("cp.async.cg.shared.global [%0], [%1], 16;" :: "r"(dst), "l"(src));
        }
        CPA_COMMIT();
    };

    float acc[2][8][4];
#pragma unroll
    for (int mt = 0; mt < 2; mt++)
#pragma unroll
        for (int nt = 0; nt < 8; nt++)
#pragma unroll
            for (int e = 0; e < 4; e++) acc[mt][nt][e] = 0.f;

    const int nch = K / KC;
    issue(0, 0);
    issue(1, 1);

    for (int ch = 0; ch < nch; ch++) {
        CPA_WAIT1();
        __syncthreads();
        if (ch + 2 < nch) issue(ch + 2, (ch + 2) % 3);
        else CPA_COMMIT();

        const float* Ah_s = smf + (ch % 3) * STAGEF;
        const float* Al_s = Ah_s + MATOFF;
        const float* Bh_s = Ah_s + 2 * MATOFF;
        const float* Bl_s = Ah_s + 3 * MATOFF;
#pragma unroll
        for (int kb = 0; kb < KC; kb += 8) {
            uint32_t ah[2][4], al[2][4], bh[8][2], bl[8][2];
#pragma unroll
            for (int mt = 0; mt < 2; mt++) {
                int r0 = (wm * 32 + mt * 16 + g) * SROW + kb + 2 * c;
                float2 lo, hi;
                lo = *reinterpret_cast<const float2*>(&Ah_s[r0]);
                hi = *reinterpret_cast<const float2*>(&Ah_s[r0 + 8 * SROW]);
                ah[mt][0] = __float_as_uint(lo.x); ah[mt][1] = __float_as_uint(hi.x);
                ah[mt][2] = __float_as_uint(lo.y); ah[mt][3] = __float_as_uint(hi.y);
                lo = *reinterpret_cast<const float2*>(&Al_s[r0]);
                hi = *reinterpret_cast<const float2*>(&Al_s[r0 + 8 * SROW]);
                al[mt][0] = __float_as_uint(lo.x); al[mt][1] = __float_as_uint(hi.x);
                al[mt][2] = __float_as_uint(lo.y); al[mt][3] = __float_as_uint(hi.y);
            }
#pragma unroll
            for (int nt = 0; nt < 8; nt++) {
                int rb = (wn * 64 + nt * 8 + g) * SROW + kb + 2 * c;
                float2 vh = *reinterpret_cast<const float2*>(&Bh_s[rb]);
                float2 vl = *reinterpret_cast<const float2*>(&Bl_s[rb]);
                bh[nt][0] = __float_as_uint(vh.x); bh[nt][1] = __float_as_uint(vh.y);
                bl[nt][0] = __float_as_uint(vl.x); bl[nt][1] = __float_as_uint(vl.y);
            }
#pragma unroll
            for (int mt = 0; mt < 2; mt++)
#pragma unroll
                for (int nt = 0; nt < 8; nt++) {
                    MMA_TF32(acc[mt][nt], ah[mt], bh[nt]);
                    MMA_TF32(acc[mt][nt], ah[mt], bl[nt]);
                    MMA_TF32(acc[mt][nt], al[mt], bh[nt]);
                }
        }
        __syncthreads();
    }

    // epilogue
    const int j0 = 2 * c, j1 = 2 * c + 1;
    const int p0 = perm8(j0), p1 = perm8(j1);
#pragma unroll
    for (int mt = 0; mt < 2; mt++) {
        int row0 = m0 + wm * 32 + mt * 16 + g;
#pragma unroll
        for (int nt = 0; nt < 8; nt++) {
            int colg = n0 + wn * 64 + nt * 8;      // 8-aligned group base
            float b0 = bias[colg + j0], b1 = bias[colg + j1];
            float v00 = acc[mt][nt][0] + b0, v01 = acc[mt][nt][1] + b1;
            float v10 = acc[mt][nt][2] + b0, v11 = acc[mt][nt][3] + b1;
            if (SPLIT) {
                uint32_t h, l;
                size_t o0 = (size_t)row0 * N + colg;
                size_t o1 = (size_t)(row0 + 8) * N + colg;
                split2(v00, h, l); Ch[o0 + p0] = __uint_as_float(h); Cl[o0 + p0] = __uint_as_float(l);
                split2(v01, h, l); Ch[o0 + p1] = __uint_as_float(h); Cl[o0 + p1] = __uint_as_float(l);
                split2(v10, h, l); Ch[o1 + p0] = __uint_as_float(h); Cl[o1 + p0] = __uint_as_float(l);
                split2(v11, h, l); Ch[o1 + p1] = __uint_as_float(h); Cl[o1 + p1] = __uint_as_float(l);
            } else {
                *reinterpret_cast<float2*>(&C[(size_t)row0 * N + colg + j0]) = make_float2(v00, v01);
                *reinterpret_cast<float2*>(&C[(size_t)(row0 + 8) * N + colg + j0]) = make_float2(v10, v11);
            }
        }
    }
}

// ---------------- assemble proposals + scores ----------------
__global__ void k_assemble(const float* __restrict__ anchd, float* __restrict__ out) {
    int row = blockIdx.x;            // b*42+e
    int b = row / NEDGE, e = row % NEDGE;
    float* prop   = out + (size_t)b * NPROP * NPRED;
    float* scores = out + (size_t)NB * NPROP * NPRED + (size_t)NB * NPROP + (size_t)b * NPROP;
    const float* rc = g_rc + (size_t)row * NPAD;
    for (int l = threadIdx.x; l < NANG * NPRED; l += blockDim.x) {
        int a = l / NPRED, q = l % NPRED;
        int p = e * NANG + a;
        float v;
        if (q < 2)      v = rc[NREG + a * 2 + q];
        else if (q < 4) v = anchd[(size_t)p * NPRED + q];
        else            v = anchd[(size_t)p * NPRED + q] + rc[a * 73 + (q - 4)];
        prop[(size_t)p * NPRED + q] = v;
    }
    if (threadIdx.x < NANG) {
        int a = threadIdx.x;
        int p = e * NANG + a;
        float l0 = rc[NREG + a * 2];
        float l1 = rc[NREG + a * 2 + 1];
        scores[p] = 1.0f / (1.0f + expf(l0 - l1));
    }
}

// ---------------- NMS: stable descending argsort + sorted gather ----------------
__global__ void k_sort(const float* __restrict__ out) {
    int b = blockIdx.x;
    __shared__ float s[NPROP];
    const float* scores = out + (size_t)NB * NPROP * NPRED + (size_t)NB * NPROP + (size_t)b * NPROP;
    const float* prop   = out + (size_t)b * NPROP * NPRED;
    for (int i = threadIdx.x; i < NPROP; i += blockDim.x) s[i] = scores[i];
    __syncthreads();
    for (int i = threadIdx.x; i < NPROP; i += blockDim.x) {
        float si = s[i];
        int r = 0;
        for (int j = 0; j < NPROP; j++) {
            float sj = s[j];
            r += (sj > si) || (sj == si && j < i);
        }
        int base = b * NPROP + r;
        g_order[base] = i;
        float p2 = prop[(size_t)i * NPRED + 2];
        float p4 = prop[(size_t)i * NPRED + 4];
        float st = fminf(fmaxf(rintf(p2 * NSTRIPSF), 0.0f), NSTRIPSF);
        float en = fminf(fmaxf(st + p4 - 1.0f, 0.0f), NSTRIPSF);
        g_sstart[base] = st;
        g_send[base]   = en;
        float* dst = g_sxs + (size_t)base * NOFF;
        const float* src = prop + (size_t)i * NPRED + 5;
        for (int k = 0; k < NOFF; k++) dst[k] = src[k];
    }
}

// ---------------- NMS: pairwise suppression bitmatrix ----------------
__global__ void k_pairs() {
    int b    = blockIdx.y;
    int warp = threadIdx.x >> 5;
    int lane = threadIdx.x & 31;
    int i    = blockIdx.x * 8 + warp;
    if (i >= NPROP) return;
    int base = b * NPROP;
    float si = g_sstart[base + i], ei = g_send[base + i];
    const float* xi = g_sxs + (size_t)(base + i) * NOFF;
    for (int jw = 0; jw < NWORDS; jw++) {
        int j = jw * 32 + lane;
        bool sup = false;
        if (j < NPROP) {
            float s  = fmaxf(si, g_sstart[base + j]);
            float e  = fminf(ei, g_send[base + j]);
            float cnt = e - s + 1.0f;
            if (cnt > 0.0f) {
                const float* xj = g_sxs + (size_t)(base + j) * NOFF;
                int k0 = (int)s;
                int k1 = (int)floorf(e);
                float sum = 0.0f;
                for (int k = k0; k <= k1; k++) sum += fabsf(xi[k] - xj[k]);
                sup = (sum / fmaxf(cnt, 1.0f)) < NMS_T;
            }
        }
        unsigned m = __ballot_sync(0xFFFFFFFFu, sup);
        if (lane == 0) g_sup[(size_t)(base + i) * NWORDS + jw] = m;
    }
}

// ---------------- NMS: sequential scan, smem-staged ----------------
__global__ __launch_bounds__(256) void k_scan(float* __restrict__ out) {
    int b = blockIdx.x;
    __shared__ unsigned ssup[2][NCHUNK][NWORDS + 1];
    __shared__ int      sorder[NPROP];
    __shared__ float    skeep [NPROP];
    int t = threadIdx.x, lane = t & 31, warp = t >> 5;
    int base = b * NPROP;
    const unsigned* gs = g_sup + (size_t)base * NWORDS;

    for (int i = t; i < NPROP; i += 256) sorder[i] = g_order[base + i];
    for (int x = t; x < NCHUNK * NWORDS; x += 256)
        ssup[0][x / NWORDS][x % NWORDS] = gs[x];
    __syncthreads();

    unsigned my = 0;
    for (int c = 0; c < NCHUNKS; c++) {
        if (warp != 0) {
            if (c + 1 < NCHUNKS) {
                int i0 = (c + 1) * NCHUNK;
                int cnt = min(NCHUNK, NPROP - i0) * NWORDS;
                int tt = t - 32;
                for (int x = tt; x < cnt; x += 224)
                    ssup[(c + 1) & 1][x / NWORDS][x % NWORDS] = gs[(size_t)i0 * NWORDS + x];
            }
        } else {
            int i1 = min(NPROP, (c + 1) * NCHUNK);
            int lw = (lane < NWORDS) ? lane : 0;
            for (int i = c * NCHUNK; i < i1; i++) {
                unsigned row = ssup[c & 1][i - c * NCHUNK][lw];
                int wi = i >> 5, bit = i & 31;
                unsigned wsup = __shfl_sync(0xFFFFFFFFu, my, wi);
                bool kept = ((wsup >> bit) & 1u) == 0u;
                if (kept) {
                    unsigned m;
                    if (lane > wi)       m = 0xFFFFFFFFu;
                    else if (lane == wi) m = (bit == 31) ? 0u : (0xFFFFFFFFu << (bit + 1));
                    else                 m = 0u;
                    my |= row & m;
                }
                if (lane == 0) skeep[sorder[i]] = kept ? 1.0f : 0.0f;
            }
        }
        __syncthreads();
    }
    float* keep = out + (size_t)NB * NPROP * NPRED + (size_t)b * NPROP;
    for (int i = t; i < NPROP; i += 256) keep[i] = skeep[i];
}

// ---------------- launcher ----------------
#define GEMM_SMEM (3 * STAGEF * 4)   // 147456 bytes

extern "C" void kernel_launch(void* const* d_in, const int* in_sizes, int n_in,
                              void* d_out, int out_size) {
    const float* feat   = (const float*)d_in[0];
    const float* W_conv = (const float*)d_in[1];
    const float* b_conv = (const float*)d_in[2];
    const float* W_cls  = (const float*)d_in[3];
    const float* b_cls  = (const float*)d_in[4];
    const float* W_reg  = (const float*)d_in[5];
    const float* b_reg  = (const float*)d_in[6];
    const float* anchd  = (const float*)d_in[8];
    float* out = (float*)d_out;

    void *pFH, *pFL, *pWH, *pWL, *pCH, *pCL, *pWcH, *pWcL, *pBc, *pRC;
    cudaGetSymbolAddress(&pFH,  g_featH);
    cudaGetSymbolAddress(&pFL,  g_featL);
    cudaGetSymbolAddress(&pWH,  g_WconvH);
    cudaGetSymbolAddress(&pWL,  g_WconvL);
    cudaGetSymbolAddress(&pCH,  g_convH);
    cudaGetSymbolAddress(&pCL,  g_convL);
    cudaGetSymbolAddress(&pWcH, g_WcH);
    cudaGetSymbolAddress(&pWcL, g_WcL);
    cudaGetSymbolAddress(&pBc,  g_bc);
    cudaGetSymbolAddress(&pRC,  g_rc);

    cudaFuncSetAttribute(k_gemm_mma<0>, cudaFuncAttributeMaxDynamicSharedMemorySize, GEMM_SMEM);
    cudaFuncSetAttribute(k_gemm_mma<1>, cudaFuncAttributeMaxDynamicSharedMemorySize, GEMM_SMEM);

    k_packW<<<(NPAD * KCONV + 255) / 256, 256>>>(W_reg, b_reg, W_cls, b_cls);
    k_splitW<<<(KCONV * KBACK + 255) / 256, 256>>>(W_conv);
    k_gather<<<(KBACK * MROWS + 255) / 256, 256>>>(feat);

    // GEMM1: feat(1408x512) @ W_conv(1024x512)^T -> convH/L (split+interleaved)
    k_gemm_mma<1><<<dim3(KCONV / 128, MPAD / 128), 256, GEMM_SMEM>>>(
        (const float*)pFH, (const float*)pFL, (const float*)pWH, (const float*)pWL,
        b_conv, nullptr, (float*)pCH, (float*)pCL, KBACK, KCONV);

    // GEMM2: conv(1408x1024) @ Wc(1280x1024)^T -> rc(1408x1280)
    k_gemm_mma<0><<<dim3(NPAD / 128, MPAD / 128), 256, GEMM_SMEM>>>(
        (const float*)pCH, (const float*)pCL, (const float*)pWcH, (const float*)pWcL,
        (const float*)pBc, (float*)pRC, nullptr, nullptr, KCONV, NPAD);

    k_assemble<<<MROWS, 256>>>(anchd, out);
    k_sort<<<NB, 256>>>(out);
    k_pairs<<<dim3((NPROP + 7) / 8, NB), 256>>>();
    k_scan<<<NB, 256>>>(out);
}

// round 9
// speedup vs baseline: 1.0299x; 1.0299x over previous
#include <cuda_runtime.h>
#include <math.h>
#include <stdint.h>

// ---------------- problem constants ----------------
#define NB      32
#define FH      11
#define FW      20
#define NEDGE   42
#define NANG    17
#define NPRED   77
#define NPROP   714
#define NOFF    72
#define KBACK   512
#define KCONV   1024
#define NREG    1241
#define NCLS    34
#define NPAD    1280        // NREG + NCLS padded to 128
#define MROWS   1344        // NB * NEDGE
#define MPAD    1408        // 11 * 128
#define NWORDS  23
#define NSTRIPSF 71.0f
#define NMS_T   15.0f
#define NCHUNK  128
#define NCHUNKS 6
#define KC      16          // K per pipeline chunk (2 k8 mma steps)
#define KSPLIT  4
#define SROW    24          // smem row stride in floats
#define MATOFF  3072        // 128 * SROW
#define STAGEF  12288       // 4 * MATOFF floats per stage

// ---------------- scratch ----------------
__device__ float    g_featH [MPAD * KBACK];     // tf32-hi edge features, k-interleaved
__device__ float    g_featL [MPAD * KBACK];
__device__ float    g_WconvH[KCONV * KBACK];
__device__ float    g_WconvL[KCONV * KBACK];
__device__ float    g_convH [MPAD * KCONV];     // gemm1 output, split + interleaved
__device__ float    g_convL [MPAD * KCONV];
__device__ float    g_WcH   [NPAD * KCONV];     // packed W_reg|W_cls, split + interleaved
__device__ float    g_WcL   [NPAD * KCONV];
__device__ float    g_bc    [NPAD];
__device__ float    g_part  [KSPLIT * MPAD * NPAD];  // K-split fp32 partials
__device__ float    g_rc    [MPAD * NPAD];      // fused reg|cls output (plain layout)
__device__ int      g_order [NB * NPROP];
__device__ float    g_sstart[NB * NPROP];
__device__ float    g_send  [NB * NPROP];
__device__ float    g_sxs   [NB * NPROP * NOFF];
__device__ unsigned g_sup   [NB * NPROP * NWORDS];

// ---------------- helpers ----------------
__device__ __forceinline__ void split2(float x, float& h, float& l) {
    uint32_t hb, lb;
    asm("cvt.rna.tf32.f32 %0, %1;" : "=r"(hb) : "f"(x));
    h = __uint_as_float(hb);
    float r = x - h;
    asm("cvt.rna.tf32.f32 %0, %1;" : "=r"(lb) : "f"(r));
    l = __uint_as_float(lb);
}
// split 8 values and store interleaved (order 0,4,1,5,2,6,3,7) as two float4s each
__device__ __forceinline__ void split8_store(const float* v, float* H, float* L) {
    float h[8], l[8];
#pragma unroll
    for (int j = 0; j < 8; j++) split2(v[j], h[j], l[j]);
    *reinterpret_cast<float4*>(H)     = make_float4(h[0], h[4], h[1], h[5]);
    *reinterpret_cast<float4*>(H + 4) = make_float4(h[2], h[6], h[3], h[7]);
    *reinterpret_cast<float4*>(L)     = make_float4(l[0], l[4], l[1], l[5]);
    *reinterpret_cast<float4*>(L + 4) = make_float4(l[2], l[6], l[3], l[7]);
}
__device__ __forceinline__ uint32_t smem_u32(const void* p) {
    uint32_t a;
    asm("{ .reg .u64 tmp; cvta.to.shared.u64 tmp, %1; cvt.u32.u64 %0, tmp; }"
        : "=r"(a) : "l"(p));
    return a;
}
#define MMA_TF32(d, a, b)                                                        \
    asm volatile("mma.sync.aligned.m16n8k8.row.col.f32.tf32.tf32.f32 "           \
        "{%0,%1,%2,%3}, {%4,%5,%6,%7}, {%8,%9}, {%0,%1,%2,%3};"                  \
        : "+f"((d)[0]), "+f"((d)[1]), "+f"((d)[2]), "+f"((d)[3])                 \
        : "r"((a)[0]), "r"((a)[1]), "r"((a)[2]), "r"((a)[3]),                    \
          "r"((b)[0]), "r"((b)[1]))
#define CPA_COMMIT() asm volatile("cp.async.commit_group;" ::: "memory")
#define CPA_WAIT1()  asm volatile("cp.async.wait_group 1;" ::: "memory")

// ---------------- pack combined weights (reg | cls | pad), split + interleave ----------------
__global__ void k_packW(const float* __restrict__ Wr, const float* __restrict__ br,
                        const float* __restrict__ Wc, const float* __restrict__ bc) {
    int i = blockIdx.x * blockDim.x + threadIdx.x;     // 8-group index
    if (i < NPAD * (KCONV / 8)) {
        int row = i >> 7, k0 = (i & 127) * 8;
        float v[8] = {0, 0, 0, 0, 0, 0, 0, 0};
        if (row < NREG) {
            *reinterpret_cast<float4*>(v)     = *reinterpret_cast<const float4*>(&Wr[(size_t)row * KCONV + k0]);
            *reinterpret_cast<float4*>(v + 4) = *reinterpret_cast<const float4*>(&Wr[(size_t)row * KCONV + k0 + 4]);
        } else if (row < NREG + NCLS) {
            *reinterpret_cast<float4*>(v)     = *reinterpret_cast<const float4*>(&Wc[(size_t)(row - NREG) * KCONV + k0]);
            *reinterpret_cast<float4*>(v + 4) = *reinterpret_cast<const float4*>(&Wc[(size_t)(row - NREG) * KCONV + k0 + 4]);
        }
        size_t o = (size_t)row * KCONV + k0;
        split8_store(v, &g_WcH[o], &g_WcL[o]);
    }
    if (i < NPAD) {
        float v = 0.f;
        if (i < NREG)             v = br[i];
        else if (i < NREG + NCLS) v = bc[i - NREG];
        g_bc[i] = v;
    }
}

// ---------------- split + interleave W_conv ----------------
__global__ void k_splitW(const float* __restrict__ W) {
    int i = blockIdx.x * blockDim.x + threadIdx.x;     // 8-group index
    if (i >= KCONV * (KBACK / 8)) return;
    size_t o = (size_t)i * 8;
    float v[8];
    *reinterpret_cast<float4*>(v)     = *reinterpret_cast<const float4*>(&W[o]);
    *reinterpret_cast<float4*>(v + 4) = *reinterpret_cast<const float4*>(&W[o + 4]);
    split8_store(v, &g_WconvH[o], &g_WconvL[o]);
}

// ---------------- gather edge features, split + interleave ----------------
__global__ void k_gather(const float* __restrict__ feat) {
    int i = blockIdx.x * blockDim.x + threadIdx.x;     // 8-group index
    if (i >= MROWS * (KBACK / 8)) return;
    int m = i >> 6, c0 = (i & 63) * 8;
    int b = m / NEDGE, e = m % NEDGE;
    int h, w;
    if (e < FH)        { h = e;      w = 0;        }
    else if (e < 2*FH) { h = e - FH; w = FW - 1;   }
    else               { h = FH - 1; w = e - 2*FH; }
    float v[8];
#pragma unroll
    for (int j = 0; j < 8; j++)
        v[j] = feat[((size_t)(b * KBACK + c0 + j) * FH + h) * FW + w];
    size_t o = (size_t)m * KBACK + c0;
    split8_store(v, &g_featH[o], &g_featL[o]);
}

// ---------------- tf32 mma.sync GEMM, 3xTF32, cp.async 3-stage, K-split x4 ----------------
// Cpart[z][m][n] = sum_{k in split z} A[m][k]*W[n][k]; operands pre-split + interleaved.
// CTA tile 128x128, 8 warps (warp tile 32x64). Term-major MMA order (RAW distance 16).
__global__ __launch_bounds__(256, 1) void k_gemm_mma(
    const float* __restrict__ Ah, const float* __restrict__ Al,
    const float* __restrict__ Bh, const float* __restrict__ Bl,
    float* __restrict__ Cpart, int K, int N)
{
    extern __shared__ float smf[];
    const uint32_t sbase = smem_u32(smf);
    const int m0 = blockIdx.y * 128, n0 = blockIdx.x * 128;
    const int t = threadIdx.x, w = t >> 5, lane = t & 31;
    const int g = lane >> 2, c = lane & 3;
    const int wm = w & 3, wn = w >> 2;          // warp tile: rows wm*32, cols wn*64
    const int kbase = blockIdx.z * (K / KSPLIT);
    const int nch = (K / KSPLIT) / KC;
    float* C = Cpart + (size_t)blockIdx.z * MPAD * N;

    const float* srcs[4] = {
        Ah + (size_t)m0 * K, Al + (size_t)m0 * K,
        Bh + (size_t)n0 * K, Bl + (size_t)n0 * K };

    auto issue = [&](int ch, int st) {
        int kb = kbase + ch * KC;
#pragma unroll
        for (int i = 0; i < 8; i++) {
            int mat = i >> 1;
            int idx = t + (i & 1) * 256;
            int row = idx >> 2, j4 = idx & 3;
            const float* src = srcs[mat] + (size_t)row * K + kb + j4 * 4;
            uint32_t dst = sbase + (uint32_t)((st * STAGEF + mat * MATOFF + row * SROW + j4 * 4) << 2);
            asm volatile("cp.async.cg.shared.global [%0], [%1], 16;" :: "r"(dst), "l"(src));
        }
        CPA_COMMIT();
    };

    float acc[2][8][4];
#pragma unroll
    for (int mt = 0; mt < 2; mt++)
#pragma unroll
        for (int nt = 0; nt < 8; nt++)
#pragma unroll
            for (int e = 0; e < 4; e++) acc[mt][nt][e] = 0.f;

    issue(0, 0);
    issue(1, 1);

    for (int ch = 0; ch < nch; ch++) {
        CPA_WAIT1();
        __syncthreads();
        if (ch + 2 < nch) issue(ch + 2, (ch + 2) % 3);
        else CPA_COMMIT();

        const float* Ah_s = smf + (ch % 3) * STAGEF;
        const float* Al_s = Ah_s + MATOFF;
        const float* Bh_s = Ah_s + 2 * MATOFF;
        const float* Bl_s = Ah_s + 3 * MATOFF;
#pragma unroll
        for (int kb = 0; kb < KC; kb += 8) {
            uint32_t ah[2][4], al[2][4], bh[8][2], bl[8][2];
#pragma unroll
            for (int mt = 0; mt < 2; mt++) {
                int r0 = (wm * 32 + mt * 16 + g) * SROW + kb + 2 * c;
                float2 lo, hi;
                lo = *reinterpret_cast<const float2*>(&Ah_s[r0]);
                hi = *reinterpret_cast<const float2*>(&Ah_s[r0 + 8 * SROW]);
                ah[mt][0] = __float_as_uint(lo.x); ah[mt][1] = __float_as_uint(hi.x);
                ah[mt][2] = __float_as_uint(lo.y); ah[mt][3] = __float_as_uint(hi.y);
                lo = *reinterpret_cast<const float2*>(&Al_s[r0]);
                hi = *reinterpret_cast<const float2*>(&Al_s[r0 + 8 * SROW]);
                al[mt][0] = __float_as_uint(lo.x); al[mt][1] = __float_as_uint(hi.x);
                al[mt][2] = __float_as_uint(lo.y); al[mt][3] = __float_as_uint(hi.y);
            }
#pragma unroll
            for (int nt = 0; nt < 8; nt++) {
                int rb = (wn * 64 + nt * 8 + g) * SROW + kb + 2 * c;
                float2 vh = *reinterpret_cast<const float2*>(&Bh_s[rb]);
                float2 vl = *reinterpret_cast<const float2*>(&Bl_s[rb]);
                bh[nt][0] = __float_as_uint(vh.x); bh[nt][1] = __float_as_uint(vh.y);
                bl[nt][0] = __float_as_uint(vl.x); bl[nt][1] = __float_as_uint(vl.y);
            }
            // term-major: accumulator RAW distance = 16 MMAs
#pragma unroll
            for (int mt = 0; mt < 2; mt++)
#pragma unroll
                for (int nt = 0; nt < 8; nt++)
                    MMA_TF32(acc[mt][nt], ah[mt], bh[nt]);
#pragma unroll
            for (int mt = 0; mt < 2; mt++)
#pragma unroll
                for (int nt = 0; nt < 8; nt++)
                    MMA_TF32(acc[mt][nt], ah[mt], bl[nt]);
#pragma unroll
            for (int mt = 0; mt < 2; mt++)
#pragma unroll
                for (int nt = 0; nt < 8; nt++)
                    MMA_TF32(acc[mt][nt], al[mt], bh[nt]);
        }
        __syncthreads();
    }

    // epilogue: raw fp32 partials (bias/split in reduce)
#pragma unroll
    for (int mt = 0; mt < 2; mt++) {
        int row0 = m0 + wm * 32 + mt * 16 + g;
#pragma unroll
        for (int nt = 0; nt < 8; nt++) {
            int col = n0 + wn * 64 + nt * 8 + 2 * c;
            *reinterpret_cast<float2*>(&C[(size_t)row0 * N + col])
                = make_float2(acc[mt][nt][0], acc[mt][nt][1]);
            *reinterpret_cast<float2*>(&C[(size_t)(row0 + 8) * N + col])
                = make_float2(acc[mt][nt][2], acc[mt][nt][3]);
        }
    }
}

// ---------------- reduce1: sum 4 partials + bias -> split+interleaved convH/L ----------------
__global__ void k_reduce1(const float* __restrict__ bias) {
    int i = blockIdx.x * blockDim.x + threadIdx.x;     // 8-group index
    if (i >= MPAD * (KCONV / 8)) return;
    size_t o = (size_t)i * 8;
    int n0 = (i & 127) * 8;                            // KCONV/8 = 128 groups per row
    float v[8];
    *reinterpret_cast<float4*>(v)     = *reinterpret_cast<const float4*>(&g_part[o]);
    *reinterpret_cast<float4*>(v + 4) = *reinterpret_cast<const float4*>(&g_part[o + 4]);
#pragma unroll
    for (int s = 1; s < KSPLIT; s++) {
        size_t so = (size_t)s * MPAD * KCONV + o;
        float4 a = *reinterpret_cast<const float4*>(&g_part[so]);
        float4 b = *reinterpret_cast<const float4*>(&g_part[so + 4]);
        v[0] += a.x; v[1] += a.y; v[2] += a.z; v[3] += a.w;
        v[4] += b.x; v[5] += b.y; v[6] += b.z; v[7] += b.w;
    }
    float4 b0 = *reinterpret_cast<const float4*>(&bias[n0]);
    float4 b1 = *reinterpret_cast<const float4*>(&bias[n0 + 4]);
    v[0] += b0.x; v[1] += b0.y; v[2] += b0.z; v[3] += b0.w;
    v[4] += b1.x; v[5] += b1.y; v[6] += b1.z; v[7] += b1.w;
    split8_store(v, &g_convH[o], &g_convL[o]);
}

// ---------------- reduce2: sum 4 partials + bias -> plain rc ----------------
__global__ void k_reduce2() {
    int i = blockIdx.x * blockDim.x + threadIdx.x;     // float4 index
    if (i >= MPAD * (NPAD / 4)) return;
    size_t o = (size_t)i * 4;
    int n0 = (i % (NPAD / 4)) * 4;
    float4 a = *reinterpret_cast<const float4*>(&g_part[o]);
#pragma unroll
    for (int s = 1; s < KSPLIT; s++) {
        float4 b = *reinterpret_cast<const float4*>(&g_part[(size_t)s * MPAD * NPAD + o]);
        a.x += b.x; a.y += b.y; a.z += b.z; a.w += b.w;
    }
    float4 bv = *reinterpret_cast<const float4*>(&g_bc[n0]);
    a.x += bv.x; a.y += bv.y; a.z += bv.z; a.w += bv.w;
    *reinterpret_cast<float4*>(&g_rc[o]) = a;
}

// ---------------- assemble proposals + scores ----------------
__global__ void k_assemble(const float* __restrict__ anchd, float* __restrict__ out) {
    int row = blockIdx.x;            // b*42+e
    int b = row / NEDGE, e = row % NEDGE;
    float* prop   = out + (size_t)b * NPROP * NPRED;
    float* scores = out + (size_t)NB * NPROP * NPRED + (size_t)NB * NPROP + (size_t)b * NPROP;
    const float* rc = g_rc + (size_t)row * NPAD;
    for (int l = threadIdx.x; l < NANG * NPRED; l += blockDim.x) {
        int a = l / NPRED, q = l % NPRED;
        int p = e * NANG + a;
        float v;
        if (q < 2)      v = rc[NREG + a * 2 + q];
        else if (q < 4) v = anchd[(size_t)p * NPRED + q];
        else            v = anchd[(size_t)p * NPRED + q] + rc[a * 73 + (q - 4)];
        prop[(size_t)p * NPRED + q] = v;
    }
    if (threadIdx.x < NANG) {
        int a = threadIdx.x;
        int p = e * NANG + a;
        float l0 = rc[NREG + a * 2];
        float l1 = rc[NREG + a * 2 + 1];
        scores[p] = 1.0f / (1.0f + expf(l0 - l1));
    }
}

// ---------------- NMS: stable descending argsort + sorted gather ----------------
__global__ void k_sort(const float* __restrict__ out) {
    int b = blockIdx.x;
    __shared__ float s[NPROP];
    const float* scores = out + (size_t)NB * NPROP * NPRED + (size_t)NB * NPROP + (size_t)b * NPROP;
    const float* prop   = out + (size_t)b * NPROP * NPRED;
    for (int i = threadIdx.x; i < NPROP; i += blockDim.x) s[i] = scores[i];
    __syncthreads();
    for (int i = threadIdx.x; i < NPROP; i += blockDim.x) {
        float si = s[i];
        int r = 0;
        for (int j = 0; j < NPROP; j++) {
            float sj = s[j];
            r += (sj > si) || (sj == si && j < i);
        }
        int base = b * NPROP + r;
        g_order[base] = i;
        float p2 = prop[(size_t)i * NPRED + 2];
        float p4 = prop[(size_t)i * NPRED + 4];
        float st = fminf(fmaxf(rintf(p2 * NSTRIPSF), 0.0f), NSTRIPSF);
        float en = fminf(fmaxf(st + p4 - 1.0f, 0.0f), NSTRIPSF);
        g_sstart[base] = st;
        g_send[base]   = en;
        float* dst = g_sxs + (size_t)base * NOFF;
        const float* src = prop + (size_t)i * NPRED + 5;
        for (int k = 0; k < NOFF; k++) dst[k] = src[k];
    }
}

// ---------------- NMS: pairwise suppression bitmatrix ----------------
__global__ void k_pairs() {
    int b    = blockIdx.y;
    int warp = threadIdx.x >> 5;
    int lane = threadIdx.x & 31;
    int i    = blockIdx.x * 8 + warp;
    if (i >= NPROP) return;
    int base = b * NPROP;
    float si = g_sstart[base + i], ei = g_send[base + i];
    const float* xi = g_sxs + (size_t)(base + i) * NOFF;
    for (int jw = 0; jw < NWORDS; jw++) {
        int j = jw * 32 + lane;
        bool sup = false;
        if (j < NPROP) {
            float s  = fmaxf(si, g_sstart[base + j]);
            float e  = fminf(ei, g_send[base + j]);
            float cnt = e - s + 1.0f;
            if (cnt > 0.0f) {
                const float* xj = g_sxs + (size_t)(base + j) * NOFF;
                int k0 = (int)s;
                int k1 = (int)floorf(e);
                float sum = 0.0f;
                for (int k = k0; k <= k1; k++) sum += fabsf(xi[k] - xj[k]);
                sup = (sum / fmaxf(cnt, 1.0f)) < NMS_T;
            }
        }
        unsigned m = __ballot_sync(0xFFFFFFFFu, sup);
        if (lane == 0) g_sup[(size_t)(base + i) * NWORDS + jw] = m;
    }
}

// ---------------- NMS: sequential scan, smem-staged ----------------
__global__ __launch_bounds__(256) void k_scan(float* __restrict__ out) {
    int b = blockIdx.x;
    __shared__ unsigned ssup[2][NCHUNK][NWORDS + 1];
    __shared__ int      sorder[NPROP];
    __shared__ float    skeep [NPROP];
    int t = threadIdx.x, lane = t & 31, warp = t >> 5;
    int base = b * NPROP;
    const unsigned* gs = g_sup + (size_t)base * NWORDS;

    for (int i = t; i < NPROP; i += 256) sorder[i] = g_order[base + i];
    for (int x = t; x < NCHUNK * NWORDS; x += 256)
        ssup[0][x / NWORDS][x % NWORDS] = gs[x];
    __syncthreads();

    unsigned my = 0;
    for (int c = 0; c < NCHUNKS; c++) {
        if (warp != 0) {
            if (c + 1 < NCHUNKS) {
                int i0 = (c + 1) * NCHUNK;
                int cnt = min(NCHUNK, NPROP - i0) * NWORDS;
                int tt = t - 32;
                for (int x = tt; x < cnt; x += 224)
                    ssup[(c + 1) & 1][x / NWORDS][x % NWORDS] = gs[(size_t)i0 * NWORDS + x];
            }
        } else {
            int i1 = min(NPROP, (c + 1) * NCHUNK);
            int lw = (lane < NWORDS) ? lane : 0;
            for (int i = c * NCHUNK; i < i1; i++) {
                unsigned row = ssup[c & 1][i - c * NCHUNK][lw];
                int wi = i >> 5, bit = i & 31;
                unsigned wsup = __shfl_sync(0xFFFFFFFFu, my, wi);
                bool kept = ((wsup >> bit) & 1u) == 0u;
                if (kept) {
                    unsigned m;
                    if (lane > wi)       m = 0xFFFFFFFFu;
                    else if (lane == wi) m = (bit == 31) ? 0u : (0xFFFFFFFFu << (bit + 1));
                    else                 m = 0u;
                    my |= row & m;
                }
                if (lane == 0) skeep[sorder[i]] = kept ? 1.0f : 0.0f;
            }
        }
        __syncthreads();
    }
    float* keep = out + (size_t)NB * NPROP * NPRED + (size_t)b * NPROP;
    for (int i = t; i < NPROP; i += 256) keep[i] = skeep[i];
}

// ---------------- launcher ----------------
#define GEMM_SMEM (3 * STAGEF * 4)   // 147456 bytes

extern "C" void kernel_launch(void* const* d_in, const int* in_sizes, int n_in,
                              void* d_out, int out_size) {
    const float* feat   = (const float*)d_in[0];
    const float* W_conv = (const float*)d_in[1];
    const float* b_conv = (const float*)d_in[2];
    const float* W_cls  = (const float*)d_in[3];
    const float* b_cls  = (const float*)d_in[4];
    const float* W_reg  = (const float*)d_in[5];
    const float* b_reg  = (const float*)d_in[6];
    const float* anchd  = (const float*)d_in[8];
    float* out = (float*)d_out;

    void *pFH, *pFL, *pWH, *pWL, *pCH, *pCL, *pWcH, *pWcL, *pPart;
    cudaGetSymbolAddress(&pFH,  g_featH);
    cudaGetSymbolAddress(&pFL,  g_featL);
    cudaGetSymbolAddress(&pWH,  g_WconvH);
    cudaGetSymbolAddress(&pWL,  g_WconvL);
    cudaGetSymbolAddress(&pCH,  g_convH);
    cudaGetSymbolAddress(&pCL,  g_convL);
    cudaGetSymbolAddress(&pWcH, g_WcH);
    cudaGetSymbolAddress(&pWcL, g_WcL);
    cudaGetSymbolAddress(&pPart, g_part);

    cudaFuncSetAttribute(k_gemm_mma, cudaFuncAttributeMaxDynamicSharedMemorySize, GEMM_SMEM);

    k_packW<<<(NPAD * (KCONV / 8) + 255) / 256, 256>>>(W_reg, b_reg, W_cls, b_cls);
    k_splitW<<<(KCONV * (KBACK / 8) + 255) / 256, 256>>>(W_conv);
    k_gather<<<(MROWS * (KBACK / 8) + 255) / 256, 256>>>(feat);

    // GEMM1: feat(1408x512) @ W_conv(1024x512)^T -> partials -> convH/L
    k_gemm_mma<<<dim3(KCONV / 128, MPAD / 128, KSPLIT), 256, GEMM_SMEM>>>(
        (const float*)pFH, (const float*)pFL, (const float*)pWH, (const float*)pWL,
        (float*)pPart, KBACK, KCONV);
    k_reduce1<<<(MPAD * (KCONV / 8) + 255) / 256, 256>>>(b_conv);

    // GEMM2: conv(1408x1024) @ Wc(1280x1024)^T -> partials -> rc
    k_gemm_mma<<<dim3(NPAD / 128, MPAD / 128, KSPLIT), 256, GEMM_SMEM>>>(
        (const float*)pCH, (const float*)pCL, (const float*)pWcH, (const float*)pWcL,
        (float*)pPart, KCONV, NPAD);
    k_reduce2<<<(MPAD * (NPAD / 4) + 255) / 256, 256>>>();

    k_assemble<<<MROWS, 256>>>(anchd, out);
    k_sort<<<NB, 256>>>(out);
    k_pairs<<<dim3((NPROP + 7) / 8, NB), 256>>>();
    k_scan<<<NB, 256>>>(out);
}

// round 10
// speedup vs baseline: 1.0879x; 1.0564x over previous
#include <cuda_runtime.h>
#include <math.h>
#include <stdint.h>

// ---------------- problem constants ----------------
#define NB      32
#define FH      11
#define FW      20
#define NEDGE   42
#define NANG    17
#define NPRED   77
#define NPROP   714
#define NOFF    72
#define KBACK   512
#define KCONV   1024
#define NREG    1241
#define NCLS    34
#define NPAD    1280        // NREG + NCLS padded to 128
#define MROWS   1344        // NB * NEDGE
#define MPAD    1408        // 11 * 128
#define NWORDS  23
#define NSTRIPSF 71.0f
#define NMS_T   15.0f
#define NCHUNK  128
#define NCHUNKS 6
#define KC      16          // K per pipeline chunk (2 k8 mma steps)
#define KSPLIT  4
#define SROW    24          // smem row stride in floats
#define MATOFF  3072        // 128 * SROW
#define STAGEF  12288       // 4 * MATOFF floats per stage

// prep kernel work partition (8-group indices)
#define PREP_W  (NPAD * (KCONV / 8))     // 163840  pack Wc
#define PREP_S  (KCONV * (KBACK / 8))    // 65536   split W_conv
#define PREP_G  (MROWS * (KBACK / 8))    // 86016   gather feat
#define PREP_TOTAL (PREP_W + PREP_S + PREP_G)

// ---------------- scratch ----------------
__device__ float    g_featH [MPAD * KBACK];
__device__ float    g_featL [MPAD * KBACK];
__device__ float    g_WconvH[KCONV * KBACK];
__device__ float    g_WconvL[KCONV * KBACK];
__device__ float    g_convH [MPAD * KCONV];
__device__ float    g_convL [MPAD * KCONV];
__device__ float    g_WcH   [NPAD * KCONV];
__device__ float    g_WcL   [NPAD * KCONV];
__device__ float    g_bc    [NPAD];
__device__ float    g_part  [KSPLIT * MPAD * NPAD];
__device__ int      g_order [NB * NPROP];
__device__ float    g_sstart[NB * NPROP];
__device__ float    g_send  [NB * NPROP];
__device__ float    g_sxs   [NB * NPROP * NOFF];
__device__ unsigned g_sup   [NB * NPROP * NWORDS];

// ---------------- helpers ----------------
__device__ __forceinline__ void split2(float x, float& h, float& l) {
    uint32_t hb, lb;
    asm("cvt.rna.tf32.f32 %0, %1;" : "=r"(hb) : "f"(x));
    h = __uint_as_float(hb);
    float r = x - h;
    asm("cvt.rna.tf32.f32 %0, %1;" : "=r"(lb) : "f"(r));
    l = __uint_as_float(lb);
}
__device__ __forceinline__ void split8_store(const float* v, float* H, float* L) {
    float h[8], l[8];
#pragma unroll
    for (int j = 0; j < 8; j++) split2(v[j], h[j], l[j]);
    *reinterpret_cast<float4*>(H)     = make_float4(h[0], h[4], h[1], h[5]);
    *reinterpret_cast<float4*>(H + 4) = make_float4(h[2], h[6], h[3], h[7]);
    *reinterpret_cast<float4*>(L)     = make_float4(l[0], l[4], l[1], l[5]);
    *reinterpret_cast<float4*>(L + 4) = make_float4(l[2], l[6], l[3], l[7]);
}
__device__ __forceinline__ uint32_t smem_u32(const void* p) {
    uint32_t a;
    asm("{ .reg .u64 tmp; cvta.to.shared.u64 tmp, %1; cvt.u32.u64 %0, tmp; }"
        : "=r"(a) : "l"(p));
    return a;
}
#define MMA_TF32(d, a, b)                                                        \
    asm volatile("mma.sync.aligned.m16n8k8.row.col.f32.tf32.tf32.f32 "           \
        "{%0,%1,%2,%3}, {%4,%5,%6,%7}, {%8,%9}, {%0,%1,%2,%3};"                  \
        : "+f"((d)[0]), "+f"((d)[1]), "+f"((d)[2]), "+f"((d)[3])                 \
        : "r"((a)[0]), "r"((a)[1]), "r"((a)[2]), "r"((a)[3]),                    \
          "r"((b)[0]), "r"((b)[1]))
#define CPA_COMMIT() asm volatile("cp.async.commit_group;" ::: "memory")
#define CPA_WAIT1()  asm volatile("cp.async.wait_group 1;" ::: "memory")

// ---------------- fused prep: packW + splitW + gather ----------------
__global__ void k_prep(const float* __restrict__ Wr, const float* __restrict__ br,
                       const float* __restrict__ Wc, const float* __restrict__ bc,
                       const float* __restrict__ Wconv, const float* __restrict__ feat) {
    int i = blockIdx.x * blockDim.x + threadIdx.x;
    if (i < PREP_W) {
        int row = i >> 7, k0 = (i & 127) * 8;
        float v[8] = {0, 0, 0, 0, 0, 0, 0, 0};
        if (row < NREG) {
            *reinterpret_cast<float4*>(v)     = *reinterpret_cast<const float4*>(&Wr[(size_t)row * KCONV + k0]);
            *reinterpret_cast<float4*>(v + 4) = *reinterpret_cast<const float4*>(&Wr[(size_t)row * KCONV + k0 + 4]);
        } else if (row < NREG + NCLS) {
            *reinterpret_cast<float4*>(v)     = *reinterpret_cast<const float4*>(&Wc[(size_t)(row - NREG) * KCONV + k0]);
            *reinterpret_cast<float4*>(v + 4) = *reinterpret_cast<const float4*>(&Wc[(size_t)(row - NREG) * KCONV + k0 + 4]);
        }
        size_t o = (size_t)row * KCONV + k0;
        split8_store(v, &g_WcH[o], &g_WcL[o]);
        if (i < NPAD) {
            float b = 0.f;
            if (i < NREG)             b = br[i];
            else if (i < NREG + NCLS) b = bc[i - NREG];
            g_bc[i] = b;
        }
        return;
    }
    i -= PREP_W;
    if (i < PREP_S) {
        size_t o = (size_t)i * 8;
        float v[8];
        *reinterpret_cast<float4*>(v)     = *reinterpret_cast<const float4*>(&Wconv[o]);
        *reinterpret_cast<float4*>(v + 4) = *reinterpret_cast<const float4*>(&Wconv[o + 4]);
        split8_store(v, &g_WconvH[o], &g_WconvL[o]);
        return;
    }
    i -= PREP_S;
    if (i < PREP_G) {
        int m = i >> 6, c0 = (i & 63) * 8;
        int b = m / NEDGE, e = m % NEDGE;
        int h, w;
        if (e < FH)        { h = e;      w = 0;        }
        else if (e < 2*FH) { h = e - FH; w = FW - 1;   }
        else               { h = FH - 1; w = e - 2*FH; }
        float v[8];
#pragma unroll
        for (int j = 0; j < 8; j++)
            v[j] = feat[((size_t)(b * KBACK + c0 + j) * FH + h) * FW + w];
        size_t o = (size_t)m * KBACK + c0;
        split8_store(v, &g_featH[o], &g_featL[o]);
    }
}

// ---------------- tf32 mma.sync GEMM, 3xTF32, cp.async 2-stage, K-split x4 ----------------
// 2 CTAs/SM (98KB smem, <=128 regs). CTA tile 128x128, warp tile 32x64, term-major.
__global__ __launch_bounds__(256, 2) void k_gemm_mma(
    const float* __restrict__ Ah, const float* __restrict__ Al,
    const float* __restrict__ Bh, const float* __restrict__ Bl,
    float* __restrict__ Cpart, int K, int N)
{
    extern __shared__ float smf[];
    const uint32_t sbase = smem_u32(smf);
    const int m0 = blockIdx.y * 128, n0 = blockIdx.x * 128;
    const int t = threadIdx.x, w = t >> 5, lane = t & 31;
    const int g = lane >> 2, c = lane & 3;
    const int wm = w & 3, wn = w >> 2;
    const int kbase = blockIdx.z * (K / KSPLIT);
    const int nch = (K / KSPLIT) / KC;
    float* C = Cpart + (size_t)blockIdx.z * MPAD * N;

    const float* srcs[4] = {
        Ah + (size_t)m0 * K, Al + (size_t)m0 * K,
        Bh + (size_t)n0 * K, Bl + (size_t)n0 * K };

    auto issue = [&](int ch, int st) {
        int kb = kbase + ch * KC;
#pragma unroll
        for (int i = 0; i < 8; i++) {
            int mat = i >> 1;
            int idx = t + (i & 1) * 256;
            int row = idx >> 2, j4 = idx & 3;
            const float* src = srcs[mat] + (size_t)row * K + kb + j4 * 4;
            uint32_t dst = sbase + (uint32_t)((st * STAGEF + mat * MATOFF + row * SROW + j4 * 4) << 2);
            asm volatile("cp.async.cg.shared.global [%0], [%1], 16;" :: "r"(dst), "l"(src));
        }
        CPA_COMMIT();
    };

    float acc[2][8][4];
#pragma unroll
    for (int mt = 0; mt < 2; mt++)
#pragma unroll
        for (int nt = 0; nt < 8; nt++)
#pragma unroll
            for (int e = 0; e < 4; e++) acc[mt][nt][e] = 0.f;

    issue(0, 0);
    issue(1, 1);

    for (int ch = 0; ch < nch; ch++) {
        CPA_WAIT1();
        __syncthreads();

        const float* Ah_s = smf + (ch & 1) * STAGEF;
        const float* Al_s = Ah_s + MATOFF;
        const float* Bh_s = Ah_s + 2 * MATOFF;
        const float* Bl_s = Ah_s + 3 * MATOFF;
#pragma unroll
        for (int kb = 0; kb < KC; kb += 8) {
            uint32_t ah[2][4], al[2][4], bh[8][2], bl[8][2];
#pragma unroll
            for (int mt = 0; mt < 2; mt++) {
                int r0 = (wm * 32 + mt * 16 + g) * SROW + kb + 2 * c;
                float2 lo, hi;
                lo = *reinterpret_cast<const float2*>(&Ah_s[r0]);
                hi = *reinterpret_cast<const float2*>(&Ah_s[r0 + 8 * SROW]);
                ah[mt][0] = __float_as_uint(lo.x); ah[mt][1] = __float_as_uint(hi.x);
                ah[mt][2] = __float_as_uint(lo.y); ah[mt][3] = __float_as_uint(hi.y);
                lo = *reinterpret_cast<const float2*>(&Al_s[r0]);
                hi = *reinterpret_cast<const float2*>(&Al_s[r0 + 8 * SROW]);
                al[mt][0] = __float_as_uint(lo.x); al[mt][1] = __float_as_uint(hi.x);
                al[mt][2] = __float_as_uint(lo.y); al[mt][3] = __float_as_uint(hi.y);
            }
#pragma unroll
            for (int nt = 0; nt < 8; nt++) {
                int rb = (wn * 64 + nt * 8 + g) * SROW + kb + 2 * c;
                float2 vh = *reinterpret_cast<const float2*>(&Bh_s[rb]);
                float2 vl = *reinterpret_cast<const float2*>(&Bl_s[rb]);
                bh[nt][0] = __float_as_uint(vh.x); bh[nt][1] = __float_as_uint(vh.y);
                bl[nt][0] = __float_as_uint(vl.x); bl[nt][1] = __float_as_uint(vl.y);
            }
#pragma unroll
            for (int mt = 0; mt < 2; mt++)
#pragma unroll
                for (int nt = 0; nt < 8; nt++)
                    MMA_TF32(acc[mt][nt], ah[mt], bh[nt]);
#pragma unroll
            for (int mt = 0; mt < 2; mt++)
#pragma unroll
                for (int nt = 0; nt < 8; nt++)
                    MMA_TF32(acc[mt][nt], ah[mt], bl[nt]);
#pragma unroll
            for (int mt = 0; mt < 2; mt++)
#pragma unroll
                for (int nt = 0; nt < 8; nt++)
                    MMA_TF32(acc[mt][nt], al[mt], bh[nt]);
        }
        __syncthreads();                       // all warps done reading stage ch&1
        if (ch + 2 < nch) issue(ch + 2, ch & 1);
        else CPA_COMMIT();                     // keep group count for WAIT1
    }

    // epilogue: raw fp32 partials
#pragma unroll
    for (int mt = 0; mt < 2; mt++) {
        int row0 = m0 + wm * 32 + mt * 16 + g;
#pragma unroll
        for (int nt = 0; nt < 8; nt++) {
            int col = n0 + wn * 64 + nt * 8 + 2 * c;
            *reinterpret_cast<float2*>(&C[(size_t)row0 * N + col])
                = make_float2(acc[mt][nt][0], acc[mt][nt][1]);
            *reinterpret_cast<float2*>(&C[(size_t)(row0 + 8) * N + col])
                = make_float2(acc[mt][nt][2], acc[mt][nt][3]);
        }
    }
}

// ---------------- reduce1: sum 4 partials + bias -> split+interleaved convH/L ----------------
__global__ void k_reduce1(const float* __restrict__ bias) {
    int i = blockIdx.x * blockDim.x + threadIdx.x;
    if (i >= MPAD * (KCONV / 8)) return;
    size_t o = (size_t)i * 8;
    int n0 = (i & 127) * 8;
    float v[8];
    *reinterpret_cast<float4*>(v)     = *reinterpret_cast<const float4*>(&g_part[o]);
    *reinterpret_cast<float4*>(v + 4) = *reinterpret_cast<const float4*>(&g_part[o + 4]);
#pragma unroll
    for (int s = 1; s < KSPLIT; s++) {
        size_t so = (size_t)s * MPAD * KCONV + o;
        float4 a = *reinterpret_cast<const float4*>(&g_part[so]);
        float4 b = *reinterpret_cast<const float4*>(&g_part[so + 4]);
        v[0] += a.x; v[1] += a.y; v[2] += a.z; v[3] += a.w;
        v[4] += b.x; v[5] += b.y; v[6] += b.z; v[7] += b.w;
    }
    float4 b0 = *reinterpret_cast<const float4*>(&bias[n0]);
    float4 b1 = *reinterpret_cast<const float4*>(&bias[n0 + 4]);
    v[0] += b0.x; v[1] += b0.y; v[2] += b0.z; v[3] += b0.w;
    v[4] += b1.x; v[5] += b1.y; v[6] += b1.z; v[7] += b1.w;
    split8_store(v, &g_convH[o], &g_convL[o]);
}

// ---------------- assemble (with inline K-split reduce of gemm2 partials) ----------------
__global__ void k_assemble(const float* __restrict__ anchd, float* __restrict__ out) {
    int row = blockIdx.x;            // b*42+e
    int b = row / NEDGE, e = row % NEDGE;
    float* prop   = out + (size_t)b * NPROP * NPRED;
    float* scores = out + (size_t)NB * NPROP * NPRED + (size_t)NB * NPROP + (size_t)b * NPROP;
    const float* p0 = g_part + (size_t)row * NPAD;
    auto rcval = [&](int n) {
        float v = g_bc[n] + p0[n];
#pragma unroll
        for (int z = 1; z < KSPLIT; z++)
            v += p0[(size_t)z * MPAD * NPAD + n];
        return v;
    };
    for (int l = threadIdx.x; l < NANG * NPRED; l += blockDim.x) {
        int a = l / NPRED, q = l % NPRED;
        int p = e * NANG + a;
        float v;
        if (q < 2)      v = rcval(NREG + a * 2 + q);
        else if (q < 4) v = anchd[(size_t)p * NPRED + q];
        else            v = anchd[(size_t)p * NPRED + q] + rcval(a * 73 + (q - 4));
        prop[(size_t)p * NPRED + q] = v;
    }
    if (threadIdx.x < NANG) {
        int a = threadIdx.x;
        int p = e * NANG + a;
        float l0 = rcval(NREG + a * 2);
        float l1 = rcval(NREG + a * 2 + 1);
        scores[p] = 1.0f / (1.0f + expf(l0 - l1));
    }
}

// ---------------- NMS: stable descending argsort + sorted gather ----------------
__global__ void k_sort(const float* __restrict__ out) {
    int b = blockIdx.x;
    __shared__ float s[NPROP];
    const float* scores = out + (size_t)NB * NPROP * NPRED + (size_t)NB * NPROP + (size_t)b * NPROP;
    const float* prop   = out + (size_t)b * NPROP * NPRED;
    for (int i = threadIdx.x; i < NPROP; i += blockDim.x) s[i] = scores[i];
    __syncthreads();
    for (int i = threadIdx.x; i < NPROP; i += blockDim.x) {
        float si = s[i];
        int r = 0;
        for (int j = 0; j < NPROP; j++) {
            float sj = s[j];
            r += (sj > si) || (sj == si && j < i);
        }
        int base = b * NPROP + r;
        g_order[base] = i;
        float p2 = prop[(size_t)i * NPRED + 2];
        float p4 = prop[(size_t)i * NPRED + 4];
        float st = fminf(fmaxf(rintf(p2 * NSTRIPSF), 0.0f), NSTRIPSF);
        float en = fminf(fmaxf(st + p4 - 1.0f, 0.0f), NSTRIPSF);
        g_sstart[base] = st;
        g_send[base]   = en;
        float* dst = g_sxs + (size_t)base * NOFF;
        const float* src = prop + (size_t)i * NPRED + 5;
        for (int k = 0; k < NOFF; k++) dst[k] = src[k];
    }
}

// ---------------- NMS: pairwise suppression bitmatrix ----------------
__global__ void k_pairs() {
    int b    = blockIdx.y;
    int warp = threadIdx.x >> 5;
    int lane = threadIdx.x & 31;
    int i    = blockIdx.x * 8 + warp;
    if (i >= NPROP) return;
    int base = b * NPROP;
    float si = g_sstart[base + i], ei = g_send[base + i];
    const float* xi = g_sxs + (size_t)(base + i) * NOFF;
    for (int jw = 0; jw < NWORDS; jw++) {
        int j = jw * 32 + lane;
        bool sup = false;
        if (j < NPROP) {
            float s  = fmaxf(si, g_sstart[base + j]);
            float e  = fminf(ei, g_send[base + j]);
            float cnt = e - s + 1.0f;
            if (cnt > 0.0f) {
                const float* xj = g_sxs + (size_t)(base + j) * NOFF;
                int k0 = (int)s;
                int k1 = (int)floorf(e);
                float sum = 0.0f;
                for (int k = k0; k <= k1; k++) sum += fabsf(xi[k] - xj[k]);
                sup = (sum / fmaxf(cnt, 1.0f)) < NMS_T;
            }
        }
        unsigned m = __ballot_sync(0xFFFFFFFFu, sup);
        if (lane == 0) g_sup[(size_t)(base + i) * NWORDS + jw] = m;
    }
}

// ---------------- NMS: sequential scan, smem-staged ----------------
__global__ __launch_bounds__(256) void k_scan(float* __restrict__ out) {
    int b = blockIdx.x;
    __shared__ unsigned ssup[2][NCHUNK][NWORDS + 1];
    __shared__ int      sorder[NPROP];
    __shared__ float    skeep [NPROP];
    int t = threadIdx.x, lane = t & 31, warp = t >> 5;
    int base = b * NPROP;
    const unsigned* gs = g_sup + (size_t)base * NWORDS;

    for (int i = t; i < NPROP; i += 256) sorder[i] = g_order[base + i];
    for (int x = t; x < NCHUNK * NWORDS; x += 256)
        ssup[0][x / NWORDS][x % NWORDS] = gs[x];
    __syncthreads();

    unsigned my = 0;
    for (int c = 0; c < NCHUNKS; c++) {
        if (warp != 0) {
            if (c + 1 < NCHUNKS) {
                int i0 = (c + 1) * NCHUNK;
                int cnt = min(NCHUNK, NPROP - i0) * NWORDS;
                int tt = t - 32;
                for (int x = tt; x < cnt; x += 224)
                    ssup[(c + 1) & 1][x / NWORDS][x % NWORDS] = gs[(size_t)i0 * NWORDS + x];
            }
        } else {
            int i1 = min(NPROP, (c + 1) * NCHUNK);
            int lw = (lane < NWORDS) ? lane : 0;
            for (int i = c * NCHUNK; i < i1; i++) {
                unsigned row = ssup[c & 1][i - c * NCHUNK][lw];
                int wi = i >> 5, bit = i & 31;
                unsigned wsup = __shfl_sync(0xFFFFFFFFu, my, wi);
                bool kept = ((wsup >> bit) & 1u) == 0u;
                if (kept) {
                    unsigned m;
                    if (lane > wi)       m = 0xFFFFFFFFu;
                    else if (lane == wi) m = (bit == 31) ? 0u : (0xFFFFFFFFu << (bit + 1));
                    else                 m = 0u;
                    my |= row & m;
                }
                if (lane == 0) skeep[sorder[i]] = kept ? 1.0f : 0.0f;
            }
        }
        __syncthreads();
    }
    float* keep = out + (size_t)NB * NPROP * NPRED + (size_t)b * NPROP;
    for (int i = t; i < NPROP; i += 256) keep[i] = skeep[i];
}

// ---------------- launcher ----------------
#define GEMM_SMEM (2 * STAGEF * 4)   // 98304 bytes

extern "C" void kernel_launch(void* const* d_in, const int* in_sizes, int n_in,
                              void* d_out, int out_size) {
    const float* feat   = (const float*)d_in[0];
    const float* W_conv = (const float*)d_in[1];
    const float* b_conv = (const float*)d_in[2];
    const float* W_cls  = (const float*)d_in[3];
    const float* b_cls  = (const float*)d_in[4];
    const float* W_reg  = (const float*)d_in[5];
    const float* b_reg  = (const float*)d_in[6];
    const float* anchd  = (const float*)d_in[8];
    float* out = (float*)d_out;

    void *pFH, *pFL, *pWH, *pWL, *pCH, *pCL, *pWcH, *pWcL, *pPart;
    cudaGetSymbolAddress(&pFH,  g_featH);
    cudaGetSymbolAddress(&pFL,  g_featL);
    cudaGetSymbolAddress(&pWH,  g_WconvH);
    cudaGetSymbolAddress(&pWL,  g_WconvL);
    cudaGetSymbolAddress(&pCH,  g_convH);
    cudaGetSymbolAddress(&pCL,  g_convL);
    cudaGetSymbolAddress(&pWcH, g_WcH);
    cudaGetSymbolAddress(&pWcL, g_WcL);
    cudaGetSymbolAddress(&pPart, g_part);

    cudaFuncSetAttribute(k_gemm_mma, cudaFuncAttributeMaxDynamicSharedMemorySize, GEMM_SMEM);

    k_prep<<<(PREP_TOTAL + 255) / 256, 256>>>(W_reg, b_reg, W_cls, b_cls, W_conv, feat);

    // GEMM1: feat(1408x512) @ W_conv(1024x512)^T -> partials -> convH/L
    k_gemm_mma<<<dim3(KCONV / 128, MPAD / 128, KSPLIT), 256, GEMM_SMEM>>>(
        (const float*)pFH, (const float*)pFL, (const float*)pWH, (const float*)pWL,
        (float*)pPart, KBACK, KCONV);
    k_reduce1<<<(MPAD * (KCONV / 8) + 255) / 256, 256>>>(b_conv);

    // GEMM2: conv(1408x1024) @ Wc(1280x1024)^T -> partials (reduced in assemble)
    k_gemm_mma<<<dim3(NPAD / 128, MPAD / 128, KSPLIT), 256, GEMM_SMEM>>>(
        (const float*)pCH, (const float*)pCL, (const float*)pWcH, (const float*)pWcL,
        (float*)pPart, KCONV, NPAD);

    k_assemble<<<MROWS, 256>>>(anchd, out);
    k_sort<<<NB, 256>>>(out);
    k_pairs<<<dim3((NPROP + 7) / 8, NB), 256>>>();
    k_scan<<<NB, 256>>>(out);
}